// round 14
// baseline (speedup 1.0000x reference)
#include <cuda_runtime.h>
#include <cuda_fp16.h>
#include <cstdint>

// ---------------------------------------------------------------------------
// SimpleGCNNet:  Y = P^2 * X * W^T + b
//   X: (2048, 2000) fp32, W: (128, 2000), b: (128,) -> Y: (32, 64, 128)
// Kernel 1 "prep" (grid 673 x 512):
//   blocks 0..511  : convert X -> g_Xh fp16 [2048][2048] (zero-padded cols)
//   blocks 512..543: convert W -> g_Wh fp16 [128][2048]
//   blocks 544..671: init Y to broadcast bias
//   block  672     : build P -> P2t (smem scratch)
// Kernel 2 "gemm" (grid 128 x 512, one wave):
//   block (mt,ks): acc = Xh[mt-slice] @ Wh^T over 512 k, fp16 mma.sync,
//   4-stage cp.async pipeline (16-k stages, depth-3 prefetch), then fused
//   tail: Y[mt] += P2 @ acc via FFMA2 + scalar atomics.
// ---------------------------------------------------------------------------

#define NNODE 64
#define GM 2048
#define GK 2000
#define GKP 2048             // padded k
#define GH 128
#define KSLICE 512
#define KITER 32             // 16-k stages per block
#define MT 64
#define THREADS 512
#define EPSW 1e-6f

// GEMM smem: 4 stages x 9216 B (stage: A 64 rows x 48B @0, B 128 rows x 48B @3072)
// tail: Zs fp32 [64][128] @0 (32768) + P2s @32768 (16384) = 49152
#define STAGE_BYTES 9216
#define SMEM_GEMM 49152
#define SMEM_PREP 36864

__device__ __align__(16) __half g_Xh[GM * GKP];      // 8 MB
__device__ __align__(16) __half g_Wh[GH * GKP];      // 512 KB
__device__ float g_P2t[NNODE * NNODE];               // [m][n] = P2[n][m]

// ---- helpers --------------------------------------------------------------
__device__ __forceinline__ uint32_t smem_u32(const void* p) {
    uint32_t a;
    asm("{ .reg .u64 t; cvta.to.shared.u64 t, %1; cvt.u32.u64 %0, t; }"
        : "=r"(a) : "l"(p));
    return a;
}
__device__ __forceinline__ unsigned long long pack2(float lo, float hi) {
    unsigned long long r;
    asm("mov.b64 %0, {%1, %2};" : "=l"(r) : "f"(lo), "f"(hi));
    return r;
}
__device__ __forceinline__ unsigned long long fma2(unsigned long long a,
                                                   unsigned long long b,
                                                   unsigned long long c) {
    unsigned long long d;
    asm("fma.rn.f32x2 %0, %1, %2, %3;" : "=l"(d) : "l"(a), "l"(b), "l"(c));
    return d;
}
__device__ __forceinline__ float2 unpack2(unsigned long long v) {
    float2 f;
    asm("mov.b64 {%0, %1}, %2;" : "=f"(f.x), "=f"(f.y) : "l"(v));
    return f;
}
__device__ __forceinline__ void ldsm4(uint32_t* r, uint32_t addr) {
    asm volatile("ldmatrix.sync.aligned.m8n8.x4.shared.b16 {%0,%1,%2,%3}, [%4];"
                 : "=r"(r[0]), "=r"(r[1]), "=r"(r[2]), "=r"(r[3]) : "r"(addr));
}
__device__ __forceinline__ void mma_f16(float* c, const uint32_t* a,
                                        uint32_t b0, uint32_t b1) {
    asm volatile(
        "mma.sync.aligned.m16n8k16.row.col.f32.f16.f16.f32 "
        "{%0,%1,%2,%3}, {%4,%5,%6,%7}, {%8,%9}, {%0,%1,%2,%3};"
        : "+f"(c[0]), "+f"(c[1]), "+f"(c[2]), "+f"(c[3])
        : "r"(a[0]), "r"(a[1]), "r"(a[2]), "r"(a[3]), "r"(b0), "r"(b1));
}
__device__ __forceinline__ void cvt_h2(float4 v, uint32_t& h0, uint32_t& h1) {
    asm("cvt.rn.f16x2.f32 %0, %1, %2;" : "=r"(h0) : "f"(v.y), "f"(v.x));
    asm("cvt.rn.f16x2.f32 %0, %1, %2;" : "=r"(h1) : "f"(v.w), "f"(v.z));
}
#define CP_ASYNC16(dst, src) \
    asm volatile("cp.async.cg.shared.global [%0], [%1], 16;" \
                 :: "r"(dst), "l"(src) : "memory")
#define CP_COMMIT() asm volatile("cp.async.commit_group;" ::: "memory")
#define CP_WAIT(n)  asm volatile("cp.async.wait_group %0;" :: "n"(n) : "memory")

// ---------------------------------------------------------------------------
// FAST build P -> P2t (512 threads). Scratch in dynamic smem:
//   P @ 0 (17408), Pt @ 17408, deg @ 34816, dinv @ 35072, flag @ 35328
// ---------------------------------------------------------------------------
#define PSTR 68
__device__ void build_p2_body(char* dsm, const int* __restrict__ eiw,
                              const float* __restrict__ ew, int E) {
    float* P    = (float*)dsm;
    float* Pt   = (float*)(dsm + 17408);
    float* deg  = (float*)(dsm + 34816);
    float* dinv = (float*)(dsm + 35072);
    int*   flag = (int*)(dsm + 35328);
    const int tid = threadIdx.x;

    for (int i = tid; i < NNODE * PSTR; i += THREADS) { P[i] = 0.0f; Pt[i] = 0.0f; }
    if (tid < NNODE) deg[tid] = 1.0f;   // self-loop weight 1.0
    if (tid == 0) *flag = 0;
    __syncthreads();

    // dtype detect: int64 little-endian values in [0,64) -> odd words == 0
    if (tid < 64 && eiw[2 * tid + 1] != 0) atomicOr(flag, 1);
    __syncthreads();
    const bool is64 = (*flag == 0);
    const bool vec_ok = ((E & 3) == 0);

    // ---- pass 1: deg ----
    for (int base = tid * 8; base < E; base += THREADS * 8) {
        if (vec_ok && base + 8 <= E) {
            int dI[8]; float wv[8];
            if (is64) {
#pragma unroll
                for (int j = 0; j < 8; j += 2) {
                    int4 u = *(const int4*)&eiw[2 * E + 2 * (base + j)];
                    dI[j] = u.x & 63; dI[j + 1] = u.z & 63;
                }
            } else {
#pragma unroll
                for (int j = 0; j < 8; j += 4) {
                    int4 u = *(const int4*)&eiw[E + base + j];
                    dI[j] = u.x & 63; dI[j + 1] = u.y & 63;
                    dI[j + 2] = u.z & 63; dI[j + 3] = u.w & 63;
                }
            }
#pragma unroll
            for (int j = 0; j < 8; j += 4)
                *(float4*)&wv[j] = *(const float4*)&ew[base + j];
#pragma unroll
            for (int j = 0; j < 8; j++) {
                float w = wv[j] <= 0.0f ? EPSW : wv[j];
                atomicAdd(&deg[dI[j]], w);
            }
        } else {
            for (int j = 0; j < 8 && base + j < E; j++) {
                int e = base + j;
                int d = (is64 ? eiw[2 * E + 2 * e] : eiw[E + e]) & 63;
                float w = ew[e]; if (w <= 0.0f) w = EPSW;
                atomicAdd(&deg[d], w);
            }
        }
    }
    __syncthreads();
    if (tid < NNODE) {
        float d = deg[tid];
        dinv[tid] = (d > 0.0f) ? rsqrtf(d) : 0.0f;
    }
    __syncthreads();

    // ---- pass 2: P / Pt ----
    for (int base = tid * 8; base < E; base += THREADS * 8) {
        if (vec_ok && base + 8 <= E) {
            int sI[8], dI[8]; float wv[8];
            if (is64) {
#pragma unroll
                for (int j = 0; j < 8; j += 2) {
                    int4 v = *(const int4*)&eiw[2 * (base + j)];
                    sI[j] = v.x & 63; sI[j + 1] = v.z & 63;
                    int4 u = *(const int4*)&eiw[2 * E + 2 * (base + j)];
                    dI[j] = u.x & 63; dI[j + 1] = u.z & 63;
                }
            } else {
#pragma unroll
                for (int j = 0; j < 8; j += 4) {
                    int4 v = *(const int4*)&eiw[base + j];
                    sI[j] = v.x & 63; sI[j + 1] = v.y & 63;
                    sI[j + 2] = v.z & 63; sI[j + 3] = v.w & 63;
                    int4 u = *(const int4*)&eiw[E + base + j];
                    dI[j] = u.x & 63; dI[j + 1] = u.y & 63;
                    dI[j + 2] = u.z & 63; dI[j + 3] = u.w & 63;
                }
            }
#pragma unroll
            for (int j = 0; j < 8; j += 4)
                *(float4*)&wv[j] = *(const float4*)&ew[base + j];
#pragma unroll
            for (int j = 0; j < 8; j++) {
                float w = wv[j] <= 0.0f ? EPSW : wv[j];
                float v = dinv[sI[j]] * w * dinv[dI[j]];
                atomicAdd(&P[dI[j] * PSTR + sI[j]], v);
                atomicAdd(&Pt[sI[j] * PSTR + dI[j]], v);
            }
        } else {
            for (int j = 0; j < 8 && base + j < E; j++) {
                int e = base + j;
                int s = (is64 ? eiw[2 * e] : eiw[e]) & 63;
                int d = (is64 ? eiw[2 * E + 2 * e] : eiw[E + e]) & 63;
                float w = ew[e]; if (w <= 0.0f) w = EPSW;
                float v = dinv[s] * w * dinv[d];
                atomicAdd(&P[d * PSTR + s], v);
                atomicAdd(&Pt[s * PSTR + d], v);
            }
        }
    }
    if (tid < NNODE) {
        float v = dinv[tid] * dinv[tid];
        atomicAdd(&P[tid * PSTR + tid], v);
        atomicAdd(&Pt[tid * PSTR + tid], v);
    }
    __syncthreads();

    // P2[r][c] = dot(P[r,:], Pt[c,:]) -> g_P2t[c*64 + r]; 8 entries/thread
    const int r = tid >> 3;
    const int cb = tid & 7;
#pragma unroll
    for (int j = 0; j < 8; j++) {
        int c = cb + 8 * j;
        float acc = 0.0f;
#pragma unroll
        for (int m = 0; m < NNODE; m += 4) {
            float4 a = *(const float4*)&P[r * PSTR + m];
            float4 bt = *(const float4*)&Pt[c * PSTR + m];
            acc += a.x * bt.x + a.y * bt.y + a.z * bt.z + a.w * bt.w;
        }
        g_P2t[c * NNODE + r] = acc;
    }
}

// ---------------------------------------------------------------------------
// Kernel 1: prep = convert X/W to fp16 (padded) + init Y + build P2
// ---------------------------------------------------------------------------
__global__ __launch_bounds__(THREADS) void prep_kernel(
    const float* __restrict__ X, const float* __restrict__ W,
    const float* __restrict__ bias,
    const int* __restrict__ eiw, const float* __restrict__ ew, int E,
    float* __restrict__ y) {

    extern __shared__ __align__(1024) char smem[];
    const int bid = blockIdx.x;
    const int tid = threadIdx.x;

    if (bid < 512 || (bid >= 512 && bid < 544)) {
        const bool isX = (bid < 512);
        const int row = (isX ? bid : bid - 512) * 4 + (tid >> 7);
        const int cb = (tid & 127) * 16;
        const float* src = (isX ? X : W) + (size_t)row * GK + cb;
        uint32_t h[8];
        if (cb < GK) {   // cb multiple of 16; 2000 = 125*16 -> full or none
#pragma unroll
            for (int i = 0; i < 4; i++) {
                float4 v = *(const float4*)(src + i * 4);
                cvt_h2(v, h[2 * i], h[2 * i + 1]);
            }
        } else {
#pragma unroll
            for (int i = 0; i < 8; i++) h[i] = 0;
        }
        __half* dst = (isX ? g_Xh : g_Wh) + (size_t)row * GKP + cb;
        *(uint4*)dst = make_uint4(h[0], h[1], h[2], h[3]);
        *(uint4*)(dst + 8) = make_uint4(h[4], h[5], h[6], h[7]);
    } else if (bid < 672) {
        const int gid = (bid - 544) * THREADS + tid;
        const int h0 = (gid * 4) & (GH - 1);
        *(float4*)(y + (size_t)gid * 4) = *(const float4*)(bias + h0);
    } else {
        build_p2_body(smem, eiw, ew, E);
    }
}

// ---------------------------------------------------------------------------
// Kernel 2: cp.async fp16 GEMM + fused P2 apply
// ---------------------------------------------------------------------------
__global__ __launch_bounds__(THREADS) void gemm_kernel(
    const float* __restrict__ bias_unused, float* __restrict__ y) {

    extern __shared__ __align__(1024) char smem[];
    const uint32_t sb = smem_u32(smem);
    const int tid = threadIdx.x;
    const int wid = tid >> 5;
    const int lane = tid & 31;

    const int mt = blockIdx.x & 31;       // batch 0..31
    const int ks = blockIdx.x >> 5;       // 0..3
    const int m_base = mt * MT;
    const int k0 = ks * KSLICE;

    // ---- copy roles: 384 threads move one 16B chunk per 16-k stage ----
    const __half* gsrc = nullptr;
    uint32_t dstoff = 0;
    if (tid < 128) {                      // A: 64 rows x 2 halves
        int row = tid >> 1, half = tid & 1;
        gsrc = g_Xh + (size_t)(m_base + row) * GKP + k0 + half * 8;
        dstoff = (uint32_t)(row * 48 + half * 16);
    } else if (tid < 384) {               // B: 128 rows x 2 halves
        int c = tid - 128, row = c >> 1, half = c & 1;
        gsrc = g_Wh + (size_t)row * GKP + k0 + half * 8;
        dstoff = (uint32_t)(3072 + row * 48 + half * 16);
    }

    auto issue = [&](int s) {
        if (tid < 384) {
            uint32_t dst = sb + (uint32_t)(s & 3) * STAGE_BYTES + dstoff;
            CP_ASYNC16(dst, gsrc + s * 16);
        }
    };

    issue(0); CP_COMMIT();
    issue(1); CP_COMMIT();
    issue(2); CP_COMMIT();

    // ---- compute roles: 16 warps = 4(m) x 4(n); warp tile 16m x 32n ----
    const int warp_m = wid >> 2, warp_n = wid & 3;
    const uint32_t lrow = (uint32_t)(lane & 15);
    const uint32_t lkh = (uint32_t)(lane >> 4) * 16;
    const uint32_t raBase = (16u * warp_m + lrow) * 48 + lkh;
    const uint32_t rbBase0 = (32u * warp_n + lrow) * 48 + lkh + 3072;
    const uint32_t rbBase1 = rbBase0 + 768u;

    float acc[16];
#pragma unroll
    for (int i = 0; i < 16; i++) acc[i] = 0.0f;

#pragma unroll 4
    for (int t = 0; t < KITER; t++) {
        CP_WAIT(2);              // stage t arrived (commit-per-iter invariant)
        __syncthreads();

        const uint32_t stA = sb + (uint32_t)(t & 3) * STAGE_BYTES;
        uint32_t Ah[4], B0[4], B1[4];
        ldsm4(Ah, stA + raBase);
        ldsm4(B0, stA + rbBase0);
        ldsm4(B1, stA + rbBase1);

        if (t + 3 < KITER) issue(t + 3);
        CP_COMMIT();             // always commit (possibly empty group)

        mma_f16(acc + 0,  Ah, B0[0], B0[2]);
        mma_f16(acc + 4,  Ah, B0[1], B0[3]);
        mma_f16(acc + 8,  Ah, B1[0], B1[2]);
        mma_f16(acc + 12, Ah, B1[1], B1[3]);
    }
    CP_WAIT(0);
    __syncthreads();   // all warps done with stage smem before reuse

    // =========================== fused P2 apply ============================
    float* Zs  = (float*)smem;            // [64][128] fp32, 32 KB
    float* P2s = (float*)(smem + 32768);  // [m][n], 16 KB

    {
        const int cr = lane >> 2, cc = (lane & 3) * 2;
        const int r0 = 16 * warp_m + cr;
#pragma unroll
        for (int nb = 0; nb < 4; nb++) {
            const float* c = acc + nb * 4;
            int col = 32 * warp_n + 8 * nb + cc;
            *(float2*)&Zs[r0 * GH + col] = make_float2(c[0], c[1]);
            *(float2*)&Zs[(r0 + 8) * GH + col] = make_float2(c[2], c[3]);
        }
    }
    for (int i = tid; i < NNODE * NNODE; i += THREADS) P2s[i] = g_P2t[i];
    __syncthreads();

    // Yp[n][h] = sum_m P2s[m*64+n] * Zs[m*128+h]; thread = 8 rows x h-pair
    const int hp = tid & 63;
    const int n0 = (tid >> 6) * 8;
    unsigned long long yacc[8];
#pragma unroll
    for (int j = 0; j < 8; j++) yacc[j] = 0ull;

#pragma unroll 4
    for (int m = 0; m < NNODE; m++) {
        unsigned long long z = *(const unsigned long long*)&Zs[m * GH + 2 * hp];
        float4 pa = *(const float4*)&P2s[m * NNODE + n0];
        float4 pb = *(const float4*)&P2s[m * NNODE + n0 + 4];
        yacc[0] = fma2(pack2(pa.x, pa.x), z, yacc[0]);
        yacc[1] = fma2(pack2(pa.y, pa.y), z, yacc[1]);
        yacc[2] = fma2(pack2(pa.z, pa.z), z, yacc[2]);
        yacc[3] = fma2(pack2(pa.w, pa.w), z, yacc[3]);
        yacc[4] = fma2(pack2(pb.x, pb.x), z, yacc[4]);
        yacc[5] = fma2(pack2(pb.y, pb.y), z, yacc[5]);
        yacc[6] = fma2(pack2(pb.z, pb.z), z, yacc[6]);
        yacc[7] = fma2(pack2(pb.w, pb.w), z, yacc[7]);
    }

    float* yb = y + ((size_t)m_base + n0) * GH + 2 * hp;
#pragma unroll
    for (int j = 0; j < 8; j++) {
        float2 v = unpack2(yacc[j]);
        atomicAdd(yb + (size_t)j * GH, v.x);
        atomicAdd(yb + (size_t)j * GH + 1, v.y);
    }
}

// ---------------------------------------------------------------------------
extern "C" void kernel_launch(void* const* d_in, const int* in_sizes, int n_in,
                              void* d_out, int out_size) {
    const float* x    = (const float*)d_in[0];
    const int*   eiw  = (const int*)d_in[1];
    const float* ew   = (const float*)d_in[2];
    const float* W    = (const float*)d_in[3];
    const float* bias = (const float*)d_in[4];
    float*       y    = (float*)d_out;

    const int E = in_sizes[1] / 2;

    static bool attr_set = false;
    if (!attr_set) {
        cudaFuncSetAttribute(gemm_kernel,
                             cudaFuncAttributeMaxDynamicSharedMemorySize,
                             SMEM_GEMM);
        cudaFuncSetAttribute(prep_kernel,
                             cudaFuncAttributeMaxDynamicSharedMemorySize,
                             SMEM_PREP);
        attr_set = true;
    }
    prep_kernel<<<673, THREADS, SMEM_PREP>>>(x, W, bias, eiw, ew, E, y);
    gemm_kernel<<<128, THREADS, SMEM_GEMM>>>(bias, y);
}

// round 15
// speedup vs baseline: 1.0009x; 1.0009x over previous
#include <cuda_runtime.h>
#include <cuda_fp16.h>
#include <cstdint>

// ---------------------------------------------------------------------------
// SimpleGCNNet:  Y = P^2 * X * W^T + b
// Kernel 1 "prep" (grid 149 x 512): block 0: build P -> P2t; blocks 1..148:
//   grid-stride convert X -> g_Xh fp16 [2048][2048] (zero-pad), W -> g_Wh,
//   init Y to broadcast bias.
// Kernel 2 "gemm" (grid 128 x 512, one wave): block (mt,ks):
//   mt 0..15 (M=128 rows = 2 batches), ks 0..7 (K=256).
//   4-stage cp.async pipeline (32-k stages, A+B together, depth-3 prefetch),
//   fp16 mma.sync (16 warps, warp tile 32m x 32n), then fused tail:
//   for both batch halves, Y += P2 @ Zpartial (packed-f32x2 FFMA + atomics).
// ---------------------------------------------------------------------------

#define NNODE 64
#define GM 2048
#define GK 2000
#define GKP 2048
#define GH 128
#define MT2 128              // rows per block (2 batches)
#define KSLICE 256
#define NITER 8              // 32-k stages
#define THREADS 512
#define EPSW 1e-6f

// stage: A 128 rows x 80 B (32k fp16 + 16B pad) @0, B same @10240 -> 20480
// 4 stages = 81920.  tail: Zs fp32[128][128] @0 (65536) + P2d @65536 (32768)
#define STAGE_BYTES 20480
#define SMEM_GEMM 98304
#define SMEM_PREP 36864

__device__ __align__(16) __half g_Xh[GM * GKP];      // 8 MB
__device__ __align__(16) __half g_Wh[GH * GKP];      // 512 KB
__device__ float g_P2t[NNODE * NNODE];               // [m][n] = P2[n][m]

// ---- helpers --------------------------------------------------------------
__device__ __forceinline__ uint32_t smem_u32(const void* p) {
    uint32_t a;
    asm("{ .reg .u64 t; cvta.to.shared.u64 t, %1; cvt.u32.u64 %0, t; }"
        : "=r"(a) : "l"(p));
    return a;
}
__device__ __forceinline__ unsigned long long pack2(float lo, float hi) {
    unsigned long long r;
    asm("mov.b64 %0, {%1, %2};" : "=l"(r) : "f"(lo), "f"(hi));
    return r;
}
__device__ __forceinline__ unsigned long long fma2(unsigned long long a,
                                                   unsigned long long b,
                                                   unsigned long long c) {
    unsigned long long d;
    asm("fma.rn.f32x2 %0, %1, %2, %3;" : "=l"(d) : "l"(a), "l"(b), "l"(c));
    return d;
}
__device__ __forceinline__ float2 unpack2(unsigned long long v) {
    float2 f;
    asm("mov.b64 {%0, %1}, %2;" : "=f"(f.x), "=f"(f.y) : "l"(v));
    return f;
}
__device__ __forceinline__ void ldsm4(uint32_t* r, uint32_t addr) {
    asm volatile("ldmatrix.sync.aligned.m8n8.x4.shared.b16 {%0,%1,%2,%3}, [%4];"
                 : "=r"(r[0]), "=r"(r[1]), "=r"(r[2]), "=r"(r[3]) : "r"(addr));
}
__device__ __forceinline__ void mma_f16(float* c, const uint32_t* a,
                                        uint32_t b0, uint32_t b1) {
    asm volatile(
        "mma.sync.aligned.m16n8k16.row.col.f32.f16.f16.f32 "
        "{%0,%1,%2,%3}, {%4,%5,%6,%7}, {%8,%9}, {%0,%1,%2,%3};"
        : "+f"(c[0]), "+f"(c[1]), "+f"(c[2]), "+f"(c[3])
        : "r"(a[0]), "r"(a[1]), "r"(a[2]), "r"(a[3]), "r"(b0), "r"(b1));
}
__device__ __forceinline__ void cvt_h2(float4 v, uint32_t& h0, uint32_t& h1) {
    asm("cvt.rn.f16x2.f32 %0, %1, %2;" : "=r"(h0) : "f"(v.y), "f"(v.x));
    asm("cvt.rn.f16x2.f32 %0, %1, %2;" : "=r"(h1) : "f"(v.w), "f"(v.z));
}
#define CP_ASYNC16(dst, src) \
    asm volatile("cp.async.cg.shared.global [%0], [%1], 16;" \
                 :: "r"(dst), "l"(src) : "memory")
#define CP_COMMIT() asm volatile("cp.async.commit_group;" ::: "memory")
#define CP_WAIT(n)  asm volatile("cp.async.wait_group %0;" :: "n"(n) : "memory")

// ---------------------------------------------------------------------------
// build P -> P2t (512 threads, smem scratch)
// ---------------------------------------------------------------------------
#define PSTR 68
__device__ void build_p2_body(char* dsm, const int* __restrict__ eiw,
                              const float* __restrict__ ew, int E) {
    float* P    = (float*)dsm;
    float* Pt   = (float*)(dsm + 17408);
    float* deg  = (float*)(dsm + 34816);
    float* dinv = (float*)(dsm + 35072);
    int*   flag = (int*)(dsm + 35328);
    const int tid = threadIdx.x;

    for (int i = tid; i < NNODE * PSTR; i += THREADS) { P[i] = 0.0f; Pt[i] = 0.0f; }
    if (tid < NNODE) deg[tid] = 1.0f;
    if (tid == 0) *flag = 0;
    __syncthreads();

    if (tid < 64 && eiw[2 * tid + 1] != 0) atomicOr(flag, 1);
    __syncthreads();
    const bool is64 = (*flag == 0);
    const bool vec_ok = ((E & 3) == 0);

    for (int base = tid * 8; base < E; base += THREADS * 8) {
        if (vec_ok && base + 8 <= E) {
            int dI[8]; float wv[8];
            if (is64) {
#pragma unroll
                for (int j = 0; j < 8; j += 2) {
                    int4 u = *(const int4*)&eiw[2 * E + 2 * (base + j)];
                    dI[j] = u.x & 63; dI[j + 1] = u.z & 63;
                }
            } else {
#pragma unroll
                for (int j = 0; j < 8; j += 4) {
                    int4 u = *(const int4*)&eiw[E + base + j];
                    dI[j] = u.x & 63; dI[j + 1] = u.y & 63;
                    dI[j + 2] = u.z & 63; dI[j + 3] = u.w & 63;
                }
            }
#pragma unroll
            for (int j = 0; j < 8; j += 4)
                *(float4*)&wv[j] = *(const float4*)&ew[base + j];
#pragma unroll
            for (int j = 0; j < 8; j++) {
                float w = wv[j] <= 0.0f ? EPSW : wv[j];
                atomicAdd(&deg[dI[j]], w);
            }
        } else {
            for (int j = 0; j < 8 && base + j < E; j++) {
                int e = base + j;
                int d = (is64 ? eiw[2 * E + 2 * e] : eiw[E + e]) & 63;
                float w = ew[e]; if (w <= 0.0f) w = EPSW;
                atomicAdd(&deg[d], w);
            }
        }
    }
    __syncthreads();
    if (tid < NNODE) {
        float d = deg[tid];
        dinv[tid] = (d > 0.0f) ? rsqrtf(d) : 0.0f;
    }
    __syncthreads();

    for (int base = tid * 8; base < E; base += THREADS * 8) {
        if (vec_ok && base + 8 <= E) {
            int sI[8], dI[8]; float wv[8];
            if (is64) {
#pragma unroll
                for (int j = 0; j < 8; j += 2) {
                    int4 v = *(const int4*)&eiw[2 * (base + j)];
                    sI[j] = v.x & 63; sI[j + 1] = v.z & 63;
                    int4 u = *(const int4*)&eiw[2 * E + 2 * (base + j)];
                    dI[j] = u.x & 63; dI[j + 1] = u.z & 63;
                }
            } else {
#pragma unroll
                for (int j = 0; j < 8; j += 4) {
                    int4 v = *(const int4*)&eiw[base + j];
                    sI[j] = v.x & 63; sI[j + 1] = v.y & 63;
                    sI[j + 2] = v.z & 63; sI[j + 3] = v.w & 63;
                    int4 u = *(const int4*)&eiw[E + base + j];
                    dI[j] = u.x & 63; dI[j + 1] = u.y & 63;
                    dI[j + 2] = u.z & 63; dI[j + 3] = u.w & 63;
                }
            }
#pragma unroll
            for (int j = 0; j < 8; j += 4)
                *(float4*)&wv[j] = *(const float4*)&ew[base + j];
#pragma unroll
            for (int j = 0; j < 8; j++) {
                float w = wv[j] <= 0.0f ? EPSW : wv[j];
                float v = dinv[sI[j]] * w * dinv[dI[j]];
                atomicAdd(&P[dI[j] * PSTR + sI[j]], v);
                atomicAdd(&Pt[sI[j] * PSTR + dI[j]], v);
            }
        } else {
            for (int j = 0; j < 8 && base + j < E; j++) {
                int e = base + j;
                int s = (is64 ? eiw[2 * e] : eiw[e]) & 63;
                int d = (is64 ? eiw[2 * E + 2 * e] : eiw[E + e]) & 63;
                float w = ew[e]; if (w <= 0.0f) w = EPSW;
                float v = dinv[s] * w * dinv[d];
                atomicAdd(&P[d * PSTR + s], v);
                atomicAdd(&Pt[s * PSTR + d], v);
            }
        }
    }
    if (tid < NNODE) {
        float v = dinv[tid] * dinv[tid];
        atomicAdd(&P[tid * PSTR + tid], v);
        atomicAdd(&Pt[tid * PSTR + tid], v);
    }
    __syncthreads();

    // P2[r][c] = dot(P[r,:], Pt[c,:]) -> g_P2t[c*64 + r] (= P2[n][m] at [m][n])
    const int r = tid >> 3;
    const int cb = tid & 7;
#pragma unroll
    for (int j = 0; j < 8; j++) {
        int c = cb + 8 * j;
        float acc = 0.0f;
#pragma unroll
        for (int m = 0; m < NNODE; m += 4) {
            float4 a = *(const float4*)&P[r * PSTR + m];
            float4 bt = *(const float4*)&Pt[c * PSTR + m];
            acc += a.x * bt.x + a.y * bt.y + a.z * bt.z + a.w * bt.w;
        }
        g_P2t[c * NNODE + r] = acc;
    }
}

// ---------------------------------------------------------------------------
// Kernel 1: prep (grid-stride convert + Y init + build)
// ---------------------------------------------------------------------------
__global__ __launch_bounds__(THREADS) void prep_kernel(
    const float* __restrict__ X, const float* __restrict__ W,
    const float* __restrict__ bias,
    const int* __restrict__ eiw, const float* __restrict__ ew, int E,
    float* __restrict__ y) {

    extern __shared__ __align__(1024) char smem[];
    if (blockIdx.x == 0) { build_p2_body(smem, eiw, ew, E); return; }

    const int nt = 148 * THREADS;
    const int gt = (blockIdx.x - 1) * THREADS + threadIdx.x;

    // X: 2048 rows x 128 chunks of 16 cols
    for (int u = gt; u < GM * 128; u += nt) {
        int row = u >> 7, ch = u & 127, cols = ch << 4;
        uint32_t h[8];
        if (ch < 125) {
            const float* src = X + (size_t)row * GK + cols;
#pragma unroll
            for (int i = 0; i < 4; i++) {
                float4 v = *(const float4*)(src + i * 4);
                cvt_h2(v, h[2 * i], h[2 * i + 1]);
            }
        } else {
#pragma unroll
            for (int i = 0; i < 8; i++) h[i] = 0;
        }
        __half* dst = g_Xh + (size_t)row * GKP + cols;
        *(uint4*)dst = make_uint4(h[0], h[1], h[2], h[3]);
        *(uint4*)(dst + 8) = make_uint4(h[4], h[5], h[6], h[7]);
    }
    // W: 128 rows x 128 chunks
    for (int u = gt; u < GH * 128; u += nt) {
        int row = u >> 7, ch = u & 127, cols = ch << 4;
        uint32_t h[8];
        if (ch < 125) {
            const float* src = W + (size_t)row * GK + cols;
#pragma unroll
            for (int i = 0; i < 4; i++) {
                float4 v = *(const float4*)(src + i * 4);
                cvt_h2(v, h[2 * i], h[2 * i + 1]);
            }
        } else {
#pragma unroll
            for (int i = 0; i < 8; i++) h[i] = 0;
        }
        __half* dst = g_Wh + (size_t)row * GKP + cols;
        *(uint4*)dst = make_uint4(h[0], h[1], h[2], h[3]);
        *(uint4*)(dst + 8) = make_uint4(h[4], h[5], h[6], h[7]);
    }
    // Y init: 65536 float4
    for (int u = gt; u < 65536; u += nt) {
        int h0 = (u * 4) & (GH - 1);
        *(float4*)(y + (size_t)u * 4) = *(const float4*)(bias + h0);
    }
}

// ---------------------------------------------------------------------------
// Kernel 2: cp.async fp16 GEMM (M=128, K=256) + fused dual-batch P2 apply
// ---------------------------------------------------------------------------
__global__ __launch_bounds__(THREADS) void gemm_kernel(float* __restrict__ y) {

    extern __shared__ __align__(1024) char smem[];
    const uint32_t sb = smem_u32(smem);
    const int tid = threadIdx.x;
    const int wid = tid >> 5;
    const int lane = tid & 31;

    const int mt = blockIdx.x & 15;       // m-tile (2 batches)
    const int ks = blockIdx.x >> 4;       // 0..7
    const int m_base = mt * MT2;
    const int k0 = ks * KSLICE;

    // copy roles: per stage each thread moves 1 A chunk + 1 B chunk (16B)
    const int crow = tid >> 2, cj = (tid & 3) * 16;        // 4 chunks/row
    const uint32_t dA = (uint32_t)(crow * 80 + cj);
    const uint32_t dB = dA + 10240u;
    const __half* srcA = g_Xh + (size_t)(m_base + crow) * GKP + k0 + cj / 2;
    const __half* srcB = g_Wh + (size_t)crow * GKP + k0 + cj / 2;

    auto issue = [&](int s) {
        uint32_t st = sb + (uint32_t)(s & 3) * STAGE_BYTES;
        CP_ASYNC16(st + dA, srcA + s * 32);
        CP_ASYNC16(st + dB, srcB + s * 32);
    };
    issue(0); CP_COMMIT();
    issue(1); CP_COMMIT();
    issue(2); CP_COMMIT();

    // compute roles: 16 warps = 4m x 4n, warp tile 32m x 32n
    const int warp_m = wid >> 2, warp_n = wid & 3;
    const uint32_t lrow = (uint32_t)(lane & 15);
    const uint32_t kh16 = (uint32_t)(lane >> 4) * 16;
    const uint32_t raA = (32u * warp_m + lrow) * 80 + kh16;            // +1280/mf, +32/g
    const uint32_t raB = (32u * warp_n + lrow) * 80 + kh16 + 10240u;   // +1280/nbh, +32/g

    float acc[32];
#pragma unroll
    for (int i = 0; i < 32; i++) acc[i] = 0.0f;

    for (int t = 0; t < NITER; t++) {
        CP_WAIT(2);
        __syncthreads();
        if (t + 3 < NITER) issue(t + 3);
        CP_COMMIT();

        const uint32_t st = sb + (uint32_t)(t & 3) * STAGE_BYTES;
        uint32_t Ah[2][2][4], Bh[2][2][4];   // [g][mf/nbh]
#pragma unroll
        for (int g = 0; g < 2; g++) {
#pragma unroll
            for (int f = 0; f < 2; f++) {
                ldsm4(Ah[g][f], st + raA + 1280u * f + 32u * g);
                ldsm4(Bh[g][f], st + raB + 1280u * f + 32u * g);
            }
        }
#pragma unroll
        for (int g = 0; g < 2; g++) {
#pragma unroll
            for (int mf = 0; mf < 2; mf++) {
#pragma unroll
                for (int nh = 0; nh < 2; nh++) {
                    float* c0 = acc + (mf * 4 + 2 * nh) * 4;
                    float* c1 = acc + (mf * 4 + 2 * nh + 1) * 4;
                    mma_f16(c0, Ah[g][mf], Bh[g][nh][0], Bh[g][nh][2]);
                    mma_f16(c1, Ah[g][mf], Bh[g][nh][1], Bh[g][nh][3]);
                }
            }
        }
    }
    CP_WAIT(0);
    __syncthreads();   // everyone done with stage smem before reuse

    // ===================== fused tail: Y += P2 @ Zpartial ===================
    float* Zs = (float*)smem;                              // [128][128] fp32
    unsigned long long* P2d = (unsigned long long*)(smem + 65536);  // packed

    {
        const int cr = lane >> 2, cc = (lane & 3) * 2;
#pragma unroll
        for (int mf = 0; mf < 2; mf++) {
#pragma unroll
            for (int nb = 0; nb < 4; nb++) {
                const float* c = acc + (mf * 4 + nb) * 4;
                int row = 32 * warp_m + 16 * mf + cr;
                int col = 32 * warp_n + 8 * nb + cc;
                *(float2*)&Zs[row * GH + col] = make_float2(c[0], c[1]);
                *(float2*)&Zs[(row + 8) * GH + col] = make_float2(c[2], c[3]);
            }
        }
    }
    // packed P2: P2d[m*64+n] = (p,p) with p = P2[n][m] = g_P2t[m*64+n]
    for (int i = tid; i < NNODE * NNODE; i += THREADS) {
        float p = g_P2t[i];
        P2d[i] = pack2(p, p);
    }
    __syncthreads();

    const int hp = tid & 63;          // h-pair
    const int n0 = (tid >> 6) * 8;    // 8 output rows
#pragma unroll
    for (int hb = 0; hb < 2; hb++) {
        unsigned long long yacc[8];
#pragma unroll
        for (int j = 0; j < 8; j++) yacc[j] = 0ull;
#pragma unroll 4
        for (int m = 0; m < NNODE; m++) {
            unsigned long long z =
                *(const unsigned long long*)&Zs[(hb * 64 + m) * GH + 2 * hp];
            const unsigned long long* pr = &P2d[m * NNODE + n0];
#pragma unroll
            for (int j = 0; j < 8; j += 2) {
                ulonglong2 pp = *(const ulonglong2*)(pr + j);
                yacc[j]     = fma2(pp.x, z, yacc[j]);
                yacc[j + 1] = fma2(pp.y, z, yacc[j + 1]);
            }
        }
        float* yb = y + ((size_t)(m_base + hb * 64) + n0) * GH + 2 * hp;
#pragma unroll
        for (int j = 0; j < 8; j++) {
            float2 v = unpack2(yacc[j]);
            atomicAdd(yb + (size_t)j * GH, v.x);
            atomicAdd(yb + (size_t)j * GH + 1, v.y);
        }
    }
}

// ---------------------------------------------------------------------------
extern "C" void kernel_launch(void* const* d_in, const int* in_sizes, int n_in,
                              void* d_out, int out_size) {
    const float* x    = (const float*)d_in[0];
    const int*   eiw  = (const int*)d_in[1];
    const float* ew   = (const float*)d_in[2];
    const float* W    = (const float*)d_in[3];
    const float* bias = (const float*)d_in[4];
    float*       y    = (float*)d_out;

    const int E = in_sizes[1] / 2;

    static bool attr_set = false;
    if (!attr_set) {
        cudaFuncSetAttribute(gemm_kernel,
                             cudaFuncAttributeMaxDynamicSharedMemorySize,
                             SMEM_GEMM);
        cudaFuncSetAttribute(prep_kernel,
                             cudaFuncAttributeMaxDynamicSharedMemorySize,
                             SMEM_PREP);
        attr_set = true;
    }
    prep_kernel<<<149, THREADS, SMEM_PREP>>>(x, W, bias, eiw, ew, E, y);
    gemm_kernel<<<128, THREADS, SMEM_GEMM>>>(y);
}

// round 16
// speedup vs baseline: 1.2696x; 1.2685x over previous
#include <cuda_runtime.h>
#include <cuda_fp16.h>
#include <cstdint>

// ---------------------------------------------------------------------------
// SimpleGCNNet:  Y = P^2 * X * W^T + b
// Kernel 0 (grid 128 x 512): Y init to broadcast bias.
// Kernel 1 (grid 257 x 256, 2 CTAs/SM):
//   blocks 0..255 = (batch mt 0..31) x (k-split ks 0..7, KSLICE=256):
//     partial = X[mt] @ W^T  (fp16 mma.sync, 8 warps 2m x 4n, 16-k stages,
//     double-buffered LDG->cvt->STS, distance-3 reg prefetch), then fused
//     tail: Y[mt] += P2 @ partial (packed FFMA2 + scalar atomics).
//   block 256: build P -> P2t (register-tiled P^2), then g_built++.
// 2 CTAs/SM hides barrier/latency stalls that capped 1-CTA variants at ~20us.
// ---------------------------------------------------------------------------

#define NNODE 64
#define GM 2048
#define GK 2000
#define GH 128
#define KSLICE 256
#define NST 16               // 16-k stages per block
#define MT 64
#define THREADS 256
#define EPSW 1e-6f

// stage: A 64 rows x 48B @0 (3072), B 128 rows x 48B @3072 (6144) = 9216
// 2 buffers = 18432.  tail: Zs fp32[64][128] @0 (32768) + P2s @32768 (16384)
#define STAGE_BYTES 9216
#define SMEM_DYN 49152

__device__ float g_P2t[NNODE * NNODE];    // [m][n] = P2[n][m]
__device__ unsigned g_built;              // sticky ready flag

// ---- helpers --------------------------------------------------------------
__device__ __forceinline__ uint32_t smem_u32(const void* p) {
    uint32_t a;
    asm("{ .reg .u64 t; cvta.to.shared.u64 t, %1; cvt.u32.u64 %0, t; }"
        : "=r"(a) : "l"(p));
    return a;
}
__device__ __forceinline__ unsigned long long pack2(float lo, float hi) {
    unsigned long long r;
    asm("mov.b64 %0, {%1, %2};" : "=l"(r) : "f"(lo), "f"(hi));
    return r;
}
__device__ __forceinline__ unsigned long long fma2(unsigned long long a,
                                                   unsigned long long b,
                                                   unsigned long long c) {
    unsigned long long d;
    asm("fma.rn.f32x2 %0, %1, %2, %3;" : "=l"(d) : "l"(a), "l"(b), "l"(c));
    return d;
}
__device__ __forceinline__ float2 unpack2(unsigned long long v) {
    float2 f;
    asm("mov.b64 {%0, %1}, %2;" : "=f"(f.x), "=f"(f.y) : "l"(v));
    return f;
}
__device__ __forceinline__ void ldsm4(uint32_t* r, uint32_t addr) {
    asm volatile("ldmatrix.sync.aligned.m8n8.x4.shared.b16 {%0,%1,%2,%3}, [%4];"
                 : "=r"(r[0]), "=r"(r[1]), "=r"(r[2]), "=r"(r[3]) : "r"(addr));
}
__device__ __forceinline__ void mma_f16(float* c, const uint32_t* a,
                                        uint32_t b0, uint32_t b1) {
    asm volatile(
        "mma.sync.aligned.m16n8k16.row.col.f32.f16.f16.f32 "
        "{%0,%1,%2,%3}, {%4,%5,%6,%7}, {%8,%9}, {%0,%1,%2,%3};"
        : "+f"(c[0]), "+f"(c[1]), "+f"(c[2]), "+f"(c[3])
        : "r"(a[0]), "r"(a[1]), "r"(a[2]), "r"(a[3]), "r"(b0), "r"(b1));
}
__device__ __forceinline__ void cvt_h2(float4 v, uint32_t& h0, uint32_t& h1) {
    asm("cvt.rn.f16x2.f32 %0, %1, %2;" : "=r"(h0) : "f"(v.y), "f"(v.x));
    asm("cvt.rn.f16x2.f32 %0, %1, %2;" : "=r"(h1) : "f"(v.w), "f"(v.z));
}
__device__ __forceinline__ void sts2(uint32_t addr, uint32_t a, uint32_t b) {
    asm volatile("st.shared.v2.b32 [%0], {%1, %2};" :: "r"(addr), "r"(a), "r"(b)
                 : "memory");
}

// ---------------------------------------------------------------------------
// build P -> P2t, register-tiled P^2 (4x4 per thread). 256 threads.
// scratch: P @0 (17408), Pt @17408, deg @34816, dinv @35072, flag @35328
// ---------------------------------------------------------------------------
#define PSTR 68
__device__ void build_p2_body(char* dsm, const int* __restrict__ eiw,
                              const float* __restrict__ ew, int E) {
    float* P    = (float*)dsm;
    float* Pt   = (float*)(dsm + 17408);
    float* deg  = (float*)(dsm + 34816);
    float* dinv = (float*)(dsm + 35072);
    int*   flag = (int*)(dsm + 35328);
    const int tid = threadIdx.x;

    for (int i = tid; i < NNODE * PSTR; i += THREADS) { P[i] = 0.0f; Pt[i] = 0.0f; }
    if (tid < NNODE) deg[tid] = 1.0f;   // self-loop weight 1.0
    if (tid == 0) *flag = 0;
    __syncthreads();

    // dtype detect: int64 little-endian values in [0,64) -> odd words == 0
    if (tid < 64 && eiw[2 * tid + 1] != 0) atomicOr(flag, 1);
    __syncthreads();
    const bool is64 = (*flag == 0);
    const bool vec_ok = ((E & 3) == 0);

    // ---- pass 1: deg ----
    for (int base = tid * 16; base < E; base += THREADS * 16) {
        if (vec_ok && base + 16 <= E) {
            int dI[16]; float wv[16];
            if (is64) {
#pragma unroll
                for (int j = 0; j < 16; j += 2) {
                    int4 u = *(const int4*)&eiw[2 * E + 2 * (base + j)];
                    dI[j] = u.x & 63; dI[j + 1] = u.z & 63;
                }
            } else {
#pragma unroll
                for (int j = 0; j < 16; j += 4) {
                    int4 u = *(const int4*)&eiw[E + base + j];
                    dI[j] = u.x & 63; dI[j + 1] = u.y & 63;
                    dI[j + 2] = u.z & 63; dI[j + 3] = u.w & 63;
                }
            }
#pragma unroll
            for (int j = 0; j < 16; j += 4)
                *(float4*)&wv[j] = *(const float4*)&ew[base + j];
#pragma unroll
            for (int j = 0; j < 16; j++) {
                float w = wv[j] <= 0.0f ? EPSW : wv[j];
                atomicAdd(&deg[dI[j]], w);
            }
        } else {
            for (int j = 0; j < 16 && base + j < E; j++) {
                int e = base + j;
                int d = (is64 ? eiw[2 * E + 2 * e] : eiw[E + e]) & 63;
                float w = ew[e]; if (w <= 0.0f) w = EPSW;
                atomicAdd(&deg[d], w);
            }
        }
    }
    __syncthreads();
    if (tid < NNODE) {
        float d = deg[tid];
        dinv[tid] = (d > 0.0f) ? rsqrtf(d) : 0.0f;
    }
    __syncthreads();

    // ---- pass 2: P / Pt ----
    for (int base = tid * 16; base < E; base += THREADS * 16) {
        if (vec_ok && base + 16 <= E) {
            int sI[16], dI[16]; float wv[16];
            if (is64) {
#pragma unroll
                for (int j = 0; j < 16; j += 2) {
                    int4 v = *(const int4*)&eiw[2 * (base + j)];
                    sI[j] = v.x & 63; sI[j + 1] = v.z & 63;
                    int4 u = *(const int4*)&eiw[2 * E + 2 * (base + j)];
                    dI[j] = u.x & 63; dI[j + 1] = u.z & 63;
                }
            } else {
#pragma unroll
                for (int j = 0; j < 16; j += 4) {
                    int4 v = *(const int4*)&eiw[base + j];
                    sI[j] = v.x & 63; sI[j + 1] = v.y & 63;
                    sI[j + 2] = v.z & 63; sI[j + 3] = v.w & 63;
                    int4 u = *(const int4*)&eiw[E + base + j];
                    dI[j] = u.x & 63; dI[j + 1] = u.y & 63;
                    dI[j + 2] = u.z & 63; dI[j + 3] = u.w & 63;
                }
            }
#pragma unroll
            for (int j = 0; j < 16; j += 4)
                *(float4*)&wv[j] = *(const float4*)&ew[base + j];
#pragma unroll
            for (int j = 0; j < 16; j++) {
                float w = wv[j] <= 0.0f ? EPSW : wv[j];
                float v = dinv[sI[j]] * w * dinv[dI[j]];
                atomicAdd(&P[dI[j] * PSTR + sI[j]], v);
                atomicAdd(&Pt[sI[j] * PSTR + dI[j]], v);
            }
        } else {
            for (int j = 0; j < 16 && base + j < E; j++) {
                int e = base + j;
                int s = (is64 ? eiw[2 * e] : eiw[e]) & 63;
                int d = (is64 ? eiw[2 * E + 2 * e] : eiw[E + e]) & 63;
                float w = ew[e]; if (w <= 0.0f) w = EPSW;
                float v = dinv[s] * w * dinv[d];
                atomicAdd(&P[d * PSTR + s], v);
                atomicAdd(&Pt[s * PSTR + d], v);
            }
        }
    }
    if (tid < NNODE) {
        float v = dinv[tid] * dinv[tid];
        atomicAdd(&P[tid * PSTR + tid], v);
        atomicAdd(&Pt[tid * PSTR + tid], v);
    }
    __syncthreads();

    // P2 register-tiled: thread (r0..r0+3) x (c0..c0+3)
    const int r0 = (tid >> 4) * 4;
    const int c0 = (tid & 15) * 4;
    float acc[4][4];
#pragma unroll
    for (int i = 0; i < 4; i++)
#pragma unroll
        for (int j = 0; j < 4; j++) acc[i][j] = 0.0f;

    for (int m = 0; m < NNODE; m += 4) {
        float4 a[4], bt[4];
#pragma unroll
        for (int i = 0; i < 4; i++) a[i] = *(const float4*)&P[(r0 + i) * PSTR + m];
#pragma unroll
        for (int j = 0; j < 4; j++) bt[j] = *(const float4*)&Pt[(c0 + j) * PSTR + m];
#pragma unroll
        for (int i = 0; i < 4; i++)
#pragma unroll
            for (int j = 0; j < 4; j++)
                acc[i][j] += a[i].x * bt[j].x + a[i].y * bt[j].y
                           + a[i].z * bt[j].z + a[i].w * bt[j].w;
    }
    // g_P2t[m][n] = P2[n][m]  => at [ (c0+j)*64 + (r0+i) ] store P2[r0+i][c0+j]
#pragma unroll
    for (int j = 0; j < 4; j++)
#pragma unroll
        for (int i = 0; i < 4; i++)
            g_P2t[(c0 + j) * NNODE + (r0 + i)] = acc[i][j];

    __syncthreads();
    if (tid == 0) {
        __threadfence();
        atomicAdd(&g_built, 1u);
    }
}

// ---------------------------------------------------------------------------
// Kernel 0: Y init to broadcast bias
// ---------------------------------------------------------------------------
__global__ __launch_bounds__(512) void init_y_kernel(
    const float* __restrict__ bias, float* __restrict__ y) {
    const int gid = blockIdx.x * 512 + threadIdx.x;
    const int h0 = (gid * 4) & (GH - 1);
    *(float4*)(y + (size_t)gid * 4) = *(const float4*)(bias + h0);
}

// ---------------------------------------------------------------------------
// Kernel 1: fused GEMM + P2-apply (256 thr, 2 CTAs/SM) + build block
// ---------------------------------------------------------------------------
__global__ void __launch_bounds__(THREADS, 2) fused_kernel(
    const float* __restrict__ X, const float* __restrict__ W,
    const int* __restrict__ eiw, const float* __restrict__ ew, int E,
    float* __restrict__ y) {

    extern __shared__ __align__(1024) char smem[];

    if (blockIdx.x == 256) { build_p2_body(smem, eiw, ew, E); return; }

    const uint32_t sb = smem_u32(smem);
    const int tid = threadIdx.x;
    const int wid = tid >> 5;
    const int lane = tid & 31;

    const int mt = blockIdx.x & 31;       // batch
    const int ks = blockIdx.x >> 5;       // 0..7
    const int m_base = mt * MT;
    const int k0 = ks * KSLICE;
    const int nst = min(NST, (GK - k0 + 15) >> 4);  // 16,...,16,13

    // loader roles per 16-k stage: X 64x16 = 256 f4 -> 1/thread;
    //                              W 128x16 = 512 f4 -> 2/thread
    const int xrow = tid >> 2, xq = (tid & 3) * 4;
    const int brow = tid >> 1, bq = (tid & 1) * 8;
    const float* xp = X + (size_t)(m_base + xrow) * GK + k0 + xq;
    const float* wp = W + (size_t)brow * GK + k0 + bq;
    const uint32_t xoff = (uint32_t)(xrow * 48 + xq * 2);
    const uint32_t boff = (uint32_t)(3072 + brow * 48 + bq * 2);

    // compute roles: 8 warps = 2m x 4n, warp tile 32m x 32n
    const int warp_m = wid >> 2, warp_n = wid & 3;

    float acc[32];
#pragma unroll
    for (int i = 0; i < 32; i++) acc[i] = 0.0f;

    const float4 fz = make_float4(0.f, 0.f, 0.f, 0.f);

    auto stsStage = [&](uint32_t st, float4 xv, float4 w0, float4 w1) {
        uint32_t h0, h1;
        cvt_h2(xv, h0, h1); sts2(st + xoff, h0, h1);
        cvt_h2(w0, h0, h1); sts2(st + boff, h0, h1);
        cvt_h2(w1, h0, h1); sts2(st + boff + 8, h0, h1);
    };
    auto ldStage = [&](int g, float4& xv, float4& w0, float4& w1) {
        bool v = (g < nst);
        int off = g * 16;
        xv = v ? *(const float4*)(xp + off) : fz;
        w0 = v ? *(const float4*)(wp + off) : fz;
        w1 = v ? *(const float4*)(wp + off + 4) : fz;
    };

    // prologue: stage 0 -> buf0; stages 1,2 into reg sets
    {
        float4 xv, w0, w1;
        ldStage(0, xv, w0, w1);
        stsStage(sb, xv, w0, w1);
    }
    float4 xr[2], wr0[2], wr1[2];
    ldStage(1, xr[1], wr0[1], wr1[1]);
    ldStage(2, xr[0], wr0[0], wr1[0]);
    __syncthreads();

    const uint32_t lrow = (uint32_t)(lane & 15);
    const uint32_t kh16 = (uint32_t)(lane >> 4) * 16;
    const uint32_t raA = (32u * warp_m + lrow) * 48 + kh16;
    const uint32_t raB = (32u * warp_n + lrow) * 48 + kh16 + 3072u;

    for (int t = 0; t < NST; t++) {
        const uint32_t st = sb + (uint32_t)(t & 1) * STAGE_BYTES;

        uint32_t Ah[2][4], Bh[2][4];
#pragma unroll
        for (int f = 0; f < 2; f++) {
            ldsm4(Ah[f], st + raA + 768u * f);
            ldsm4(Bh[f], st + raB + 768u * f);
        }

        if (t + 1 < NST) {
            const int s = (t + 1) & 1;
            stsStage(sb + (uint32_t)s * STAGE_BYTES, xr[s], wr0[s], wr1[s]);
        }
        if (t + 3 < NST) {
            const int s = (t + 3) & 1;
            ldStage(t + 3, xr[s], wr0[s], wr1[s]);
        }
        __syncthreads();

#pragma unroll
        for (int mf = 0; mf < 2; mf++) {
#pragma unroll
            for (int nh = 0; nh < 2; nh++) {
                float* c0 = acc + (mf * 4 + 2 * nh) * 4;
                float* c1 = acc + (mf * 4 + 2 * nh + 1) * 4;
                mma_f16(c0, Ah[mf], Bh[nh][0], Bh[nh][2]);
                mma_f16(c1, Ah[mf], Bh[nh][1], Bh[nh][3]);
            }
        }
    }
    __syncthreads();   // done with stage smem

    // ===================== fused tail: Y += P2 @ partial ====================
    float* Zs  = (float*)smem;            // [64][128] fp32
    float* P2s = (float*)(smem + 32768);  // [m][n]

    {
        const int cr = lane >> 2, cc = (lane & 3) * 2;
#pragma unroll
        for (int mf = 0; mf < 2; mf++) {
#pragma unroll
            for (int nb = 0; nb < 4; nb++) {
                const float* c = acc + (mf * 4 + nb) * 4;
                int row = 32 * warp_m + 16 * mf + cr;
                int col = 32 * warp_n + 8 * nb + cc;
                *(float2*)&Zs[row * GH + col] = make_float2(c[0], c[1]);
                *(float2*)&Zs[(row + 8) * GH + col] = make_float2(c[2], c[3]);
            }
        }
    }
    if (tid == 0) {
        while (atomicAdd(&g_built, 0u) == 0u) { }   // first launch only
        __threadfence();
    }
    __syncthreads();
    for (int i = tid; i < NNODE * NNODE; i += THREADS) P2s[i] = g_P2t[i];
    __syncthreads();

    const int hp = tid & 63;          // h-pair
    const int n0 = (tid >> 6) * 16;   // 16 output rows
    unsigned long long yacc[16];
#pragma unroll
    for (int j = 0; j < 16; j++) yacc[j] = 0ull;

#pragma unroll 4
    for (int m = 0; m < NNODE; m++) {
        unsigned long long z = *(const unsigned long long*)&Zs[m * GH + 2 * hp];
        const float* pr = &P2s[m * NNODE + n0];
#pragma unroll
        for (int j = 0; j < 16; j += 4) {
            float4 p4 = *(const float4*)(pr + j);
            yacc[j + 0] = fma2(pack2(p4.x, p4.x), z, yacc[j + 0]);
            yacc[j + 1] = fma2(pack2(p4.y, p4.y), z, yacc[j + 1]);
            yacc[j + 2] = fma2(pack2(p4.z, p4.z), z, yacc[j + 2]);
            yacc[j + 3] = fma2(pack2(p4.w, p4.w), z, yacc[j + 3]);
        }
    }

    float* yb = y + ((size_t)m_base + n0) * GH + 2 * hp;
#pragma unroll
    for (int j = 0; j < 16; j++) {
        float2 v = unpack2(yacc[j]);
        atomicAdd(yb + (size_t)j * GH, v.x);
        atomicAdd(yb + (size_t)j * GH + 1, v.y);
    }
}

// ---------------------------------------------------------------------------
extern "C" void kernel_launch(void* const* d_in, const int* in_sizes, int n_in,
                              void* d_out, int out_size) {
    const float* x    = (const float*)d_in[0];
    const int*   eiw  = (const int*)d_in[1];
    const float* ew   = (const float*)d_in[2];
    const float* W    = (const float*)d_in[3];
    const float* bias = (const float*)d_in[4];
    float*       y    = (float*)d_out;

    const int E = in_sizes[1] / 2;

    static bool attr_set = false;
    if (!attr_set) {
        cudaFuncSetAttribute(fused_kernel,
                             cudaFuncAttributeMaxDynamicSharedMemorySize,
                             SMEM_DYN);
        attr_set = true;
    }
    init_y_kernel<<<128, 512>>>(bias, y);
    fused_kernel<<<257, THREADS, SMEM_DYN>>>(x, W, eiw, ew, E, y);
}